// round 1
// baseline (speedup 1.0000x reference)
#include <cuda_runtime.h>
#include <cstdint>

#define Dd 1024
#define Bb 32
#define Ss 2048
#define Mtot (Bb * Ss)      // 65536
#define BLK_M 128
#define BLK_N 64
#define BLK_K 32
#define NTILES (Dd / BLK_N) // 16

// Scratch (allocation-free rule: __device__ globals)
__device__ float g_Hq[Bb * Dd];                 // 128 KB
__device__ float g_partial[NTILES * Mtot];      // 4 MB

__device__ __forceinline__ float tanh_fast(float x) {
    float y;
    asm("tanh.approx.f32 %0, %1;" : "=f"(y) : "f"(x));
    return y;
}

__device__ __forceinline__ float to_tf32(float x) {
    float y;
    asm("cvt.rna.tf32.f32 %0, %1;" : "=f"(y) : "f"(x));
    return y;
}

__device__ __forceinline__ void mma_tf32(float (&d)[4], const uint32_t (&a)[4],
                                         const uint32_t (&b)[2]) {
    asm volatile(
        "mma.sync.aligned.m16n8k8.row.col.f32.tf32.tf32.f32 "
        "{%0,%1,%2,%3}, {%4,%5,%6,%7}, {%8,%9}, {%0,%1,%2,%3};"
        : "+f"(d[0]), "+f"(d[1]), "+f"(d[2]), "+f"(d[3])
        : "r"(a[0]), "r"(a[1]), "r"(a[2]), "r"(a[3]), "r"(b[0]), "r"(b[1]));
}

// ---------------------------------------------------------------------------
// Kernel 1: Hq[b,n] = bias[n] + sum_k hidden[b,k] * W[k,n]   (W_top rows)
// grid: (4, 32)  block: 256   (n = bx*256+tid, b = by)
// ---------------------------------------------------------------------------
__global__ void prep_kernel(const float* __restrict__ hidden,
                            const float* __restrict__ W,
                            const float* __restrict__ bias) {
    const int b = blockIdx.y;
    const int n = blockIdx.x * 256 + threadIdx.x;
    __shared__ float h[Dd];
    for (int i = threadIdx.x; i < Dd; i += 256) h[i] = hidden[b * Dd + i];
    __syncthreads();
    float acc = bias[n];
#pragma unroll 8
    for (int k = 0; k < Dd; k++) {
        acc = fmaf(h[k], W[(size_t)k * Dd + n], acc);
    }
    g_Hq[b * Dd + n] = acc;
}

// ---------------------------------------------------------------------------
// Kernel 2: fused GEMM + tanh + v-dot partial reduction
//   partial[nt][m] = sum_{n in tile nt} v[n]*tanh(Hq[b,n] + E[m,:]@Wbot[:,n])
// grid: (16, 512)  block: 256 (8 warps: 4 along M, 2 along N)
// ---------------------------------------------------------------------------
__global__ __launch_bounds__(256, 2)
void fused_gemm_kernel(const float* __restrict__ E,
                       const float* __restrict__ W,
                       const float* __restrict__ v) {
    __shared__ float Es[BLK_M * 36];  // stride 36 (≡4 mod 32) -> conflict-free A loads
    __shared__ float Ws[BLK_K * 72];  // stride 72 (≡8 mod 32) -> conflict-free B loads
    __shared__ float sums[BLK_M * 2];

    const int tid = threadIdx.x;
    const int wid = tid >> 5;
    const int lane = tid & 31;
    const int g = lane >> 2;    // groupID
    const int tig = lane & 3;   // thread-in-group
    const int warp_m = wid & 3;
    const int warp_n = wid >> 2;

    const int m0 = blockIdx.y * BLK_M;
    const int n0 = blockIdx.x * BLK_N;
    const int b = m0 >> 11;     // m0 / 2048

    const float* __restrict__ Wb = W + (size_t)Dd * Dd;  // bottom half of W

    float acc[2][4][4];
#pragma unroll
    for (int mf = 0; mf < 2; mf++)
#pragma unroll
        for (int nf = 0; nf < 4; nf++)
#pragma unroll
            for (int i = 0; i < 4; i++) acc[mf][nf][i] = 0.f;

    for (int kt = 0; kt < Dd; kt += BLK_K) {
        // --- stage E tile [128 x 32] (fp32 -> tf32-rounded) ---
#pragma unroll
        for (int i = 0; i < 4; i++) {
            int f = tid + i * 256;          // 0..1023
            int row = f >> 3;
            int c4 = (f & 7) << 2;
            float4 val = *reinterpret_cast<const float4*>(
                E + (size_t)(m0 + row) * Dd + kt + c4);
            float* p = &Es[row * 36 + c4];
            p[0] = to_tf32(val.x); p[1] = to_tf32(val.y);
            p[2] = to_tf32(val.z); p[3] = to_tf32(val.w);
        }
        // --- stage W tile [32 x 64] ---
#pragma unroll
        for (int i = 0; i < 2; i++) {
            int f = tid + i * 256;          // 0..511
            int row = f >> 4;
            int c4 = (f & 15) << 2;
            float4 val = *reinterpret_cast<const float4*>(
                Wb + (size_t)(kt + row) * Dd + n0 + c4);
            float* p = &Ws[row * 72 + c4];
            p[0] = to_tf32(val.x); p[1] = to_tf32(val.y);
            p[2] = to_tf32(val.z); p[3] = to_tf32(val.w);
        }
        __syncthreads();

#pragma unroll
        for (int kk = 0; kk < BLK_K; kk += 8) {
            uint32_t afrag[2][4], bfrag[4][2];
#pragma unroll
            for (int mf = 0; mf < 2; mf++) {
                int r0 = warp_m * 32 + mf * 16 + g;
                afrag[mf][0] = __float_as_uint(Es[r0 * 36 + kk + tig]);
                afrag[mf][1] = __float_as_uint(Es[(r0 + 8) * 36 + kk + tig]);
                afrag[mf][2] = __float_as_uint(Es[r0 * 36 + kk + tig + 4]);
                afrag[mf][3] = __float_as_uint(Es[(r0 + 8) * 36 + kk + tig + 4]);
            }
#pragma unroll
            for (int nf = 0; nf < 4; nf++) {
                int c = warp_n * 32 + nf * 8 + g;
                bfrag[nf][0] = __float_as_uint(Ws[(kk + tig) * 72 + c]);
                bfrag[nf][1] = __float_as_uint(Ws[(kk + tig + 4) * 72 + c]);
            }
#pragma unroll
            for (int mf = 0; mf < 2; mf++)
#pragma unroll
                for (int nf = 0; nf < 4; nf++)
                    mma_tf32(acc[mf][nf], afrag[mf], bfrag[nf]);
        }
        __syncthreads();
    }

    // --- epilogue: tanh + v-weighted row reduction ---
    float hq[8], vv[8];
#pragma unroll
    for (int nf = 0; nf < 4; nf++)
#pragma unroll
        for (int j = 0; j < 2; j++) {
            int c = n0 + warp_n * 32 + nf * 8 + 2 * tig + j;
            hq[nf * 2 + j] = g_Hq[b * Dd + c];
            vv[nf * 2 + j] = v[c];
        }

    float psum[4] = {0.f, 0.f, 0.f, 0.f};  // [mf*2 + rowhalf]
#pragma unroll
    for (int mf = 0; mf < 2; mf++)
#pragma unroll
        for (int nf = 0; nf < 4; nf++)
#pragma unroll
            for (int i = 0; i < 4; i++) {
                int half = i >> 1;   // row half (g vs g+8)
                int j = i & 1;       // col parity
                float e = tanh_fast(acc[mf][nf][i] + hq[nf * 2 + j]);
                psum[mf * 2 + half] = fmaf(e, vv[nf * 2 + j], psum[mf * 2 + half]);
            }
    // reduce across the 4 threads of each group (tig bits = lane bits 0,1)
#pragma unroll
    for (int r = 0; r < 4; r++) {
        psum[r] += __shfl_xor_sync(0xffffffffu, psum[r], 1);
        psum[r] += __shfl_xor_sync(0xffffffffu, psum[r], 2);
    }
    if (tig == 0) {
#pragma unroll
        for (int r = 0; r < 4; r++) {
            int mf = r >> 1, half = r & 1;
            int lrow = warp_m * 32 + mf * 16 + half * 8 + g;
            sums[lrow * 2 + warp_n] = psum[r];
        }
    }
    __syncthreads();
    if (tid < BLK_M) {
        float t = sums[tid * 2] + sums[tid * 2 + 1];
        g_partial[(size_t)blockIdx.x * Mtot + m0 + tid] = t;
    }
}

// ---------------------------------------------------------------------------
// Kernel 3: sum partials, mask, softmax per batch row
// grid: 32  block: 256
// ---------------------------------------------------------------------------
__global__ void softmax_kernel(const int* __restrict__ src_len,
                               float* __restrict__ out) {
    const int b = blockIdx.x;
    const int len = src_len[b];
    const int tid = threadIdx.x;
    __shared__ float sc[Ss];
    __shared__ float red[256];

    float lmax = -3.0e38f;
    for (int s = tid; s < Ss; s += 256) {
        float val = 0.f;
#pragma unroll
        for (int t = 0; t < NTILES; t++)
            val += g_partial[(size_t)t * Mtot + b * Ss + s];
        if (s >= len) val = -3.0e38f;
        sc[s] = val;
        lmax = fmaxf(lmax, val);
    }
    red[tid] = lmax;
    __syncthreads();
    for (int o = 128; o > 0; o >>= 1) {
        if (tid < o) red[tid] = fmaxf(red[tid], red[tid + o]);
        __syncthreads();
    }
    const float gmax = red[0];
    __syncthreads();

    float lsum = 0.f;
    for (int s = tid; s < Ss; s += 256) {
        float e = (s < len) ? __expf(sc[s] - gmax) : 0.f;
        sc[s] = e;
        lsum += e;
    }
    red[tid] = lsum;
    __syncthreads();
    for (int o = 128; o > 0; o >>= 1) {
        if (tid < o) red[tid] += red[tid + o];
        __syncthreads();
    }
    const float inv = 1.f / red[0];
    __syncthreads();
    for (int s = tid; s < Ss; s += 256) out[b * Ss + s] = sc[s] * inv;
}

// ---------------------------------------------------------------------------
extern "C" void kernel_launch(void* const* d_in, const int* in_sizes, int n_in,
                              void* d_out, int out_size) {
    const float* hidden  = (const float*)d_in[0];
    const float* enc     = (const float*)d_in[1];
    const float* W       = (const float*)d_in[2];
    const float* bias    = (const float*)d_in[3];
    const float* v       = (const float*)d_in[4];
    const int*   src_len = (const int*)d_in[5];
    float* out = (float*)d_out;

    prep_kernel<<<dim3(4, 32), 256>>>(hidden, W, bias);
    fused_gemm_kernel<<<dim3(NTILES, Mtot / BLK_M), 256>>>(enc, W, v);
    softmax_kernel<<<Bb, 256>>>(src_len, out);
}

// round 3
// speedup vs baseline: 1.4129x; 1.4129x over previous
#include <cuda_runtime.h>
#include <cstdint>

#define Dd 1024
#define Bb 32
#define Ss 2048
#define Mtot (Bb * Ss)          // 65536
#define M_TILE 128
#define N_TILE 128
#define K_TILE 32
#define NSTG 3
#define NTILES (Dd / N_TILE)    // 8
#define NCHUNK (Dd / K_TILE)    // 32

#define A_STRIDE 36             // floats; bank-conflict-free, 16B-aligned rows
#define B_STRIDE 136

// byte offsets in dynamic smem
#define OFF_HQ   0
#define OFF_V    512
#define STAGE_BYTES (M_TILE * A_STRIDE * 4 + K_TILE * B_STRIDE * 4)  // 18432+17408
#define OFF_A(s) (1024 + (s) * STAGE_BYTES)
#define OFF_B(s) (OFF_A(s) + M_TILE * A_STRIDE * 4)
#define SMEM_BYTES (1024 + NSTG * STAGE_BYTES)   // 108544

__device__ float g_Hq[Bb * Dd];
__device__ float g_partial[NTILES * Mtot];       // 2 MB

__device__ __forceinline__ float tanh_fast(float x) {
    float y; asm("tanh.approx.f32 %0, %1;" : "=f"(y) : "f"(x)); return y;
}
__device__ __forceinline__ uint32_t ld_tf32(const float* p) {
    float x = *p;
    float y;
    asm("cvt.rna.tf32.f32 %0, %1;" : "=f"(y) : "f"(x));
    return __float_as_uint(y);
}
__device__ __forceinline__ void mma_tf32(float (&d)[4], const uint32_t (&a)[4],
                                         const uint32_t (&b)[2]) {
    asm volatile(
        "mma.sync.aligned.m16n8k8.row.col.f32.tf32.tf32.f32 "
        "{%0,%1,%2,%3}, {%4,%5,%6,%7}, {%8,%9}, {%0,%1,%2,%3};"
        : "+f"(d[0]), "+f"(d[1]), "+f"(d[2]), "+f"(d[3])
        : "r"(a[0]), "r"(a[1]), "r"(a[2]), "r"(a[3]), "r"(b[0]), "r"(b[1]));
}
__device__ __forceinline__ void cp_async16(uint32_t dst, const void* src) {
    asm volatile("cp.async.cg.shared.global [%0], [%1], 16;"
                 :: "r"(dst), "l"(src) : "memory");
}
__device__ __forceinline__ void cp_commit() {
    asm volatile("cp.async.commit_group;" ::: "memory");
}
__device__ __forceinline__ void cp_wait1() {
    asm volatile("cp.async.wait_group 1;" ::: "memory");
}
__device__ __forceinline__ uint32_t smem_u32(const void* p) {
    uint32_t a;
    asm("{ .reg .u64 t; cvta.to.shared.u64 t, %1; cvt.u32.u64 %0, t; }"
        : "=r"(a) : "l"(p));
    return a;
}

// ---------------------------------------------------------------------------
// Kernel 1: Hq[b,n] = bias[n] + sum_k hidden[b,k]*W[k,n]  (top half of W)
// grid (32, 32), block 256: 8-way K split per output column
// ---------------------------------------------------------------------------
__global__ void prep_kernel(const float* __restrict__ hidden,
                            const float* __restrict__ W,
                            const float* __restrict__ bias) {
    __shared__ float h[Dd];
    __shared__ float red[256];
    const int b = blockIdx.y;
    const int n0 = blockIdx.x * 32;
    const int t = threadIdx.x;
    {
        float4 v4 = *reinterpret_cast<const float4*>(hidden + b * Dd + t * 4);
        h[t * 4 + 0] = v4.x; h[t * 4 + 1] = v4.y;
        h[t * 4 + 2] = v4.z; h[t * 4 + 3] = v4.w;
    }
    __syncthreads();
    const int n = n0 + (t & 31);
    const int kbeg = (t >> 5) * 128;
    float acc = 0.f;
#pragma unroll 8
    for (int k = kbeg; k < kbeg + 128; k++)
        acc = fmaf(h[k], W[(size_t)k * Dd + n], acc);
    red[t] = acc;
    __syncthreads();
    if (t < 32) {
        float s = bias[n0 + t];
#pragma unroll
        for (int j = 0; j < 8; j++) s += red[j * 32 + t];
        g_Hq[b * Dd + n0 + t] = s;
    }
}

// ---------------------------------------------------------------------------
// Kernel 2: pipelined tf32 GEMM (mma.sync) + fused tanh/v-dot epilogue
// grid (8, 512), block 256 (8 warps: 4 along M, 2 along N), 2 CTAs/SM
// ---------------------------------------------------------------------------
__global__ __launch_bounds__(256, 2)
void gemm_tanh_kernel(const float* __restrict__ E,
                      const float* __restrict__ W,
                      const float* __restrict__ v) {
    extern __shared__ __align__(1024) char smem[];
    const uint32_t sb = smem_u32(smem);

    const int tid = threadIdx.x;
    const int wid = tid >> 5;
    const int lane = tid & 31;
    const int g = lane >> 2;
    const int tig = lane & 3;
    const int warp_m = wid & 3;
    const int warp_n = wid >> 2;

    const int n0 = blockIdx.x * N_TILE;
    const int m0 = blockIdx.y * M_TILE;
    const int b = blockIdx.y >> 4;      // 2048/128 = 16 m-tiles per batch

    const float* __restrict__ Wb = W + (size_t)Dd * Dd;

    // stage hq/v for epilogue
    float* hq_s = reinterpret_cast<float*>(smem + OFF_HQ);
    float* v_s  = reinterpret_cast<float*>(smem + OFF_V);
    if (tid < N_TILE) {
        hq_s[tid] = g_Hq[b * Dd + n0 + tid];
        v_s[tid]  = v[n0 + tid];
    }

    // per-thread copy indices (A: 1024 16B-chunks, B: 1024 16B-chunks)
    // A: row = id>>3, chunk = id&7 ; B: row = id>>5, chunk = id&31
    auto issue_stage = [&](int i) {
        const int kt = i * K_TILE;
        const int s = i % NSTG;
        const uint32_t abase = sb + OFF_A(s);
        const uint32_t bbase = sb + OFF_B(s);
#pragma unroll
        for (int p = 0; p < 4; p++) {
            int id = tid + p * 256;
            int row = id >> 3, ch = id & 7;
            cp_async16(abase + row * (A_STRIDE * 4) + ch * 16,
                       E + (size_t)(m0 + row) * Dd + kt + ch * 4);
        }
#pragma unroll
        for (int p = 0; p < 4; p++) {
            int id = tid + p * 256;
            int row = id >> 5, ch = id & 31;
            cp_async16(bbase + row * (B_STRIDE * 4) + ch * 16,
                       Wb + (size_t)(kt + row) * Dd + n0 + ch * 4);
        }
        cp_commit();
    };

    issue_stage(0);
    issue_stage(1);

    float acc[2][8][4];
#pragma unroll
    for (int mf = 0; mf < 2; mf++)
#pragma unroll
        for (int nf = 0; nf < 8; nf++)
#pragma unroll
            for (int i = 0; i < 4; i++) acc[mf][nf][i] = 0.f;

    for (int i = 0; i < NCHUNK; i++) {
        cp_wait1();
        __syncthreads();
        if (i + 2 < NCHUNK) issue_stage(i + 2);

        const int s = i % NSTG;
        const float* As = reinterpret_cast<const float*>(smem + OFF_A(s));
        const float* Bs = reinterpret_cast<const float*>(smem + OFF_B(s));

#pragma unroll
        for (int kk = 0; kk < K_TILE; kk += 8) {
            uint32_t afrag[2][4], bfrag[8][2];
#pragma unroll
            for (int mf = 0; mf < 2; mf++) {
                const int r0 = warp_m * 32 + mf * 16 + g;
                afrag[mf][0] = ld_tf32(&As[r0 * A_STRIDE + kk + tig]);
                afrag[mf][1] = ld_tf32(&As[(r0 + 8) * A_STRIDE + kk + tig]);
                afrag[mf][2] = ld_tf32(&As[r0 * A_STRIDE + kk + tig + 4]);
                afrag[mf][3] = ld_tf32(&As[(r0 + 8) * A_STRIDE + kk + tig + 4]);
            }
#pragma unroll
            for (int nf = 0; nf < 8; nf++) {
                const int c = warp_n * 64 + nf * 8 + g;
                bfrag[nf][0] = ld_tf32(&Bs[(kk + tig) * B_STRIDE + c]);
                bfrag[nf][1] = ld_tf32(&Bs[(kk + tig + 4) * B_STRIDE + c]);
            }
#pragma unroll
            for (int mf = 0; mf < 2; mf++)
#pragma unroll
                for (int nf = 0; nf < 8; nf++)
                    mma_tf32(acc[mf][nf], afrag[mf], bfrag[nf]);
        }
        __syncthreads();
    }

    // ---- epilogue: tanh + v-weighted row reduction ----
    float hq[16], vv[16];
#pragma unroll
    for (int nf = 0; nf < 8; nf++)
#pragma unroll
        for (int j = 0; j < 2; j++) {
            const int c = warp_n * 64 + nf * 8 + 2 * tig + j;
            hq[nf * 2 + j] = hq_s[c];
            vv[nf * 2 + j] = v_s[c];
        }

    float psum[4] = {0.f, 0.f, 0.f, 0.f};
#pragma unroll
    for (int mf = 0; mf < 2; mf++)
#pragma unroll
        for (int nf = 0; nf < 8; nf++)
#pragma unroll
            for (int i = 0; i < 4; i++) {
                const int half = i >> 1;
                const int j = i & 1;
                float e = tanh_fast(acc[mf][nf][i] + hq[nf * 2 + j]);
                psum[mf * 2 + half] = fmaf(e, vv[nf * 2 + j], psum[mf * 2 + half]);
            }
#pragma unroll
    for (int r = 0; r < 4; r++) {
        psum[r] += __shfl_xor_sync(0xffffffffu, psum[r], 1);
        psum[r] += __shfl_xor_sync(0xffffffffu, psum[r], 2);
    }

    __syncthreads();  // stage buffers dead; reuse as reduction scratch
    float* sums = reinterpret_cast<float*>(smem + OFF_A(0));
    if (tig == 0) {
#pragma unroll
        for (int r = 0; r < 4; r++) {
            const int mf = r >> 1, half = r & 1;
            const int lrow = warp_m * 32 + mf * 16 + half * 8 + g;
            sums[lrow * 2 + warp_n] = psum[r];
        }
    }
    __syncthreads();
    if (tid < M_TILE)
        g_partial[(size_t)blockIdx.x * Mtot + m0 + tid] =
            sums[tid * 2] + sums[tid * 2 + 1];
}

// ---------------------------------------------------------------------------
// Kernel 3: sum partials, mask, softmax per batch row
// ---------------------------------------------------------------------------
__global__ void softmax_kernel(const int* __restrict__ src_len,
                               float* __restrict__ out) {
    const int b = blockIdx.x;
    const int len = src_len[b];
    const int tid = threadIdx.x;
    __shared__ float sc[Ss];
    __shared__ float red[256];

    float lmax = -3.0e38f;
    for (int s = tid; s < Ss; s += 256) {
        float val = 0.f;
#pragma unroll
        for (int t = 0; t < NTILES; t++)
            val += g_partial[(size_t)t * Mtot + b * Ss + s];
        if (s >= len) val = -3.0e38f;
        sc[s] = val;
        lmax = fmaxf(lmax, val);
    }
    red[tid] = lmax;
    __syncthreads();
    for (int o = 128; o > 0; o >>= 1) {
        if (tid < o) red[tid] = fmaxf(red[tid], red[tid + o]);
        __syncthreads();
    }
    const float gmax = red[0];
    __syncthreads();

    float lsum = 0.f;
    for (int s = tid; s < Ss; s += 256) {
        float e = (s < len) ? __expf(sc[s] - gmax) : 0.f;
        sc[s] = e;
        lsum += e;
    }
    red[tid] = lsum;
    __syncthreads();
    for (int o = 128; o > 0; o >>= 1) {
        if (tid < o) red[tid] += red[tid + o];
        __syncthreads();
    }
    const float inv = 1.f / red[0];
    __syncthreads();
    for (int s = tid; s < Ss; s += 256) out[b * Ss + s] = sc[s] * inv;
}

// ---------------------------------------------------------------------------
extern "C" void kernel_launch(void* const* d_in, const int* in_sizes, int n_in,
                              void* d_out, int out_size) {
    const float* hidden  = (const float*)d_in[0];
    const float* enc     = (const float*)d_in[1];
    const float* W       = (const float*)d_in[2];
    const float* bias    = (const float*)d_in[3];
    const float* v       = (const float*)d_in[4];
    const int*   src_len = (const int*)d_in[5];
    float* out = (float*)d_out;

    cudaFuncSetAttribute(gemm_tanh_kernel,
                         cudaFuncAttributeMaxDynamicSharedMemorySize, SMEM_BYTES);

    prep_kernel<<<dim3(32, 32), 256>>>(hidden, W, bias);
    gemm_tanh_kernel<<<dim3(NTILES, Mtot / M_TILE), 256, SMEM_BYTES>>>(enc, W, v);
    softmax_kernel<<<Bb, 256>>>(src_len, out);
}

// round 4
// speedup vs baseline: 1.7111x; 1.2111x over previous
#include <cuda_runtime.h>
#include <cstdint>

#define Dd 1024
#define Bb 32
#define Ss 2048
#define Mtot (Bb * Ss)          // 65536
#define M_TILE 128
#define N_TILE 128
#define K_TILE 32
#define NSTG 3
#define NTILES (Dd / N_TILE)    // 8
#define NCHUNK (Dd / K_TILE)    // 32

#define A_STRIDE 36             // floats; conflict-free, 16B-aligned rows
#define B_STRIDE 136

#define OFF_HQ   0
#define OFF_V    512
#define STAGE_BYTES (M_TILE * A_STRIDE * 4 + K_TILE * B_STRIDE * 4)  // 35840
#define OFF_A(s) (1024 + (s) * STAGE_BYTES)
#define OFF_B(s) (OFF_A(s) + M_TILE * A_STRIDE * 4)
#define SMEM_BYTES (1024 + NSTG * STAGE_BYTES)   // 108544

__device__ float g_Hq[Bb * Dd];
__device__ float g_Wt[Dd * Dd];                  // tf32-rounded bottom W (4 MB)
__device__ float g_partial[NTILES * Mtot];       // 2 MB

__device__ __forceinline__ float tanh_fast(float x) {
    float y; asm("tanh.approx.f32 %0, %1;" : "=f"(y) : "f"(x)); return y;
}
__device__ __forceinline__ float rna_tf32(float x) {
    float y; asm("cvt.rna.tf32.f32 %0, %1;" : "=f"(y) : "f"(x)); return y;
}
__device__ __forceinline__ uint32_t ld_tf32(const float* p) {
    return __float_as_uint(rna_tf32(*p));
}
__device__ __forceinline__ void mma_tf32(float (&d)[4], const uint32_t (&a)[4],
                                         const uint32_t (&b)[2]) {
    asm volatile(
        "mma.sync.aligned.m16n8k8.row.col.f32.tf32.tf32.f32 "
        "{%0,%1,%2,%3}, {%4,%5,%6,%7}, {%8,%9}, {%0,%1,%2,%3};"
        : "+f"(d[0]), "+f"(d[1]), "+f"(d[2]), "+f"(d[3])
        : "r"(a[0]), "r"(a[1]), "r"(a[2]), "r"(a[3]), "r"(b[0]), "r"(b[1]));
}
__device__ __forceinline__ void cp_async16(uint32_t dst, const void* src) {
    asm volatile("cp.async.cg.shared.global [%0], [%1], 16;"
                 :: "r"(dst), "l"(src) : "memory");
}
__device__ __forceinline__ void cp_commit() {
    asm volatile("cp.async.commit_group;" ::: "memory");
}
__device__ __forceinline__ void cp_wait1() {
    asm volatile("cp.async.wait_group 1;" ::: "memory");
}
__device__ __forceinline__ uint32_t smem_u32(const void* p) {
    uint32_t a;
    asm("{ .reg .u64 t; cvta.to.shared.u64 t, %1; cvt.u32.u64 %0, t; }"
        : "=r"(a) : "l"(p));
    return a;
}

// ---------------------------------------------------------------------------
// Kernel 0: g_Wt = tf32_rna(W_bottom)   (grid 1024, block 256)
// ---------------------------------------------------------------------------
__global__ void wconv_kernel(const float* __restrict__ W) {
    const float* Wb = W + (size_t)Dd * Dd;
    const int i = (blockIdx.x * 256 + threadIdx.x) * 4;
    float4 x = *reinterpret_cast<const float4*>(Wb + i);
    x.x = rna_tf32(x.x); x.y = rna_tf32(x.y);
    x.z = rna_tf32(x.z); x.w = rna_tf32(x.w);
    *reinterpret_cast<float4*>(g_Wt + i) = x;
}

// ---------------------------------------------------------------------------
// Kernel 1: Hq[b,n] = bias[n] + sum_k hidden[b,k]*W[k,n]  (top half of W)
// ---------------------------------------------------------------------------
__global__ void prep_kernel(const float* __restrict__ hidden,
                            const float* __restrict__ W,
                            const float* __restrict__ bias) {
    __shared__ float h[Dd];
    __shared__ float red[256];
    const int b = blockIdx.y;
    const int n0 = blockIdx.x * 32;
    const int t = threadIdx.x;
    {
        float4 v4 = *reinterpret_cast<const float4*>(hidden + b * Dd + t * 4);
        h[t * 4 + 0] = v4.x; h[t * 4 + 1] = v4.y;
        h[t * 4 + 2] = v4.z; h[t * 4 + 3] = v4.w;
    }
    __syncthreads();
    const int n = n0 + (t & 31);
    const int kbeg = (t >> 5) * 128;
    float acc = 0.f;
#pragma unroll 8
    for (int k = kbeg; k < kbeg + 128; k++)
        acc = fmaf(h[k], W[(size_t)k * Dd + n], acc);
    red[t] = acc;
    __syncthreads();
    if (t < 32) {
        float s = bias[n0 + t];
#pragma unroll
        for (int j = 0; j < 8; j++) s += red[j * 32 + t];
        g_Hq[b * Dd + n0 + t] = s;
    }
}

// ---------------------------------------------------------------------------
// Kernel 2: pipelined tf32 GEMM, 4 warps of 64x64, + fused tanh/v-dot
// grid (8, 512), block 128, 2 CTAs/SM
// ---------------------------------------------------------------------------
__global__ __launch_bounds__(128, 2)
void gemm_tanh_kernel(const float* __restrict__ E,
                      const float* __restrict__ v) {
    extern __shared__ __align__(1024) char smem[];
    const uint32_t sb = smem_u32(smem);

    const int tid = threadIdx.x;
    const int wid = tid >> 5;
    const int lane = tid & 31;
    const int g = lane >> 2;
    const int tig = lane & 3;
    const int warp_m = wid & 1;        // 2 warps along M (64 rows each)
    const int warp_n = wid >> 1;       // 2 warps along N (64 cols each)

    const int n0 = blockIdx.x * N_TILE;
    const int m0 = blockIdx.y * M_TILE;
    const int b = blockIdx.y >> 4;

    float* hq_s = reinterpret_cast<float*>(smem + OFF_HQ);
    float* v_s  = reinterpret_cast<float*>(smem + OFF_V);
    hq_s[tid] = g_Hq[b * Dd + n0 + tid];
    v_s[tid]  = v[n0 + tid];

    auto issue_stage = [&](int i) {
        const int kt = i * K_TILE;
        const int s = i % NSTG;
        const uint32_t abase = sb + OFF_A(s);
        const uint32_t bbase = sb + OFF_B(s);
#pragma unroll
        for (int p = 0; p < 8; p++) {
            int id = tid + p * 128;
            int row = id >> 3, ch = id & 7;
            cp_async16(abase + row * (A_STRIDE * 4) + ch * 16,
                       E + (size_t)(m0 + row) * Dd + kt + ch * 4);
        }
#pragma unroll
        for (int p = 0; p < 8; p++) {
            int id = tid + p * 128;
            int row = id >> 5, ch = id & 31;
            cp_async16(bbase + row * (B_STRIDE * 4) + ch * 16,
                       g_Wt + (size_t)(kt + row) * Dd + n0 + ch * 4);
        }
        cp_commit();
    };

    issue_stage(0);
    issue_stage(1);

    float acc[4][8][4];
#pragma unroll
    for (int mf = 0; mf < 4; mf++)
#pragma unroll
        for (int nf = 0; nf < 8; nf++)
#pragma unroll
            for (int i = 0; i < 4; i++) acc[mf][nf][i] = 0.f;

    for (int i = 0; i < NCHUNK; i++) {
        cp_wait1();
        __syncthreads();
        if (i + 2 < NCHUNK) issue_stage(i + 2);

        const int s = i % NSTG;
        const float* As = reinterpret_cast<const float*>(smem + OFF_A(s));
        const float* Bs = reinterpret_cast<const float*>(smem + OFF_B(s));

#pragma unroll
        for (int kk = 0; kk < K_TILE; kk += 8) {
            uint32_t afrag[4][4], bfrag[8][2];
#pragma unroll
            for (int mf = 0; mf < 4; mf++) {
                const int r0 = warp_m * 64 + mf * 16 + g;
                afrag[mf][0] = ld_tf32(&As[r0 * A_STRIDE + kk + tig]);
                afrag[mf][1] = ld_tf32(&As[(r0 + 8) * A_STRIDE + kk + tig]);
                afrag[mf][2] = ld_tf32(&As[r0 * A_STRIDE + kk + tig + 4]);
                afrag[mf][3] = ld_tf32(&As[(r0 + 8) * A_STRIDE + kk + tig + 4]);
            }
#pragma unroll
            for (int nf = 0; nf < 8; nf++) {
                const int c = warp_n * 64 + nf * 8 + g;
                bfrag[nf][0] = __float_as_uint(Bs[(kk + tig) * B_STRIDE + c]);
                bfrag[nf][1] = __float_as_uint(Bs[(kk + tig + 4) * B_STRIDE + c]);
            }
#pragma unroll
            for (int mf = 0; mf < 4; mf++)
#pragma unroll
                for (int nf = 0; nf < 8; nf++)
                    mma_tf32(acc[mf][nf], afrag[mf], bfrag[nf]);
        }
        __syncthreads();
    }

    // ---- epilogue: tanh + v-weighted row reduction ----
    float hq[16], vv[16];
#pragma unroll
    for (int nf = 0; nf < 8; nf++)
#pragma unroll
        for (int j = 0; j < 2; j++) {
            const int c = warp_n * 64 + nf * 8 + 2 * tig + j;
            hq[nf * 2 + j] = hq_s[c];
            vv[nf * 2 + j] = v_s[c];
        }

    float psum[8];
#pragma unroll
    for (int r = 0; r < 8; r++) psum[r] = 0.f;
#pragma unroll
    for (int mf = 0; mf < 4; mf++)
#pragma unroll
        for (int nf = 0; nf < 8; nf++)
#pragma unroll
            for (int i = 0; i < 4; i++) {
                const int half = i >> 1;
                const int j = i & 1;
                float e = tanh_fast(acc[mf][nf][i] + hq[nf * 2 + j]);
                psum[mf * 2 + half] = fmaf(e, vv[nf * 2 + j], psum[mf * 2 + half]);
            }
#pragma unroll
    for (int r = 0; r < 8; r++) {
        psum[r] += __shfl_xor_sync(0xffffffffu, psum[r], 1);
        psum[r] += __shfl_xor_sync(0xffffffffu, psum[r], 2);
    }

    __syncthreads();
    float* sums = reinterpret_cast<float*>(smem + OFF_A(0));
    if (tig == 0) {
#pragma unroll
        for (int r = 0; r < 8; r++) {
            const int mf = r >> 1, half = r & 1;
            const int lrow = warp_m * 64 + mf * 16 + half * 8 + g;
            sums[lrow * 2 + warp_n] = psum[r];
        }
    }
    __syncthreads();
    g_partial[(size_t)blockIdx.x * Mtot + m0 + tid] =
        sums[tid * 2] + sums[tid * 2 + 1];
}

// ---------------------------------------------------------------------------
// Kernel 3: sum partials, mask, softmax per batch row
// ---------------------------------------------------------------------------
__global__ void softmax_kernel(const int* __restrict__ src_len,
                               float* __restrict__ out) {
    const int b = blockIdx.x;
    const int len = src_len[b];
    const int tid = threadIdx.x;
    __shared__ float sc[Ss];
    __shared__ float red[256];

    float lmax = -3.0e38f;
    for (int s = tid; s < Ss; s += 256) {
        float val = 0.f;
#pragma unroll
        for (int t = 0; t < NTILES; t++)
            val += g_partial[(size_t)t * Mtot + b * Ss + s];
        if (s >= len) val = -3.0e38f;
        sc[s] = val;
        lmax = fmaxf(lmax, val);
    }
    red[tid] = lmax;
    __syncthreads();
    for (int o = 128; o > 0; o >>= 1) {
        if (tid < o) red[tid] = fmaxf(red[tid], red[tid + o]);
        __syncthreads();
    }
    const float gmax = red[0];
    __syncthreads();

    float lsum = 0.f;
    for (int s = tid; s < Ss; s += 256) {
        float e = (s < len) ? __expf(sc[s] - gmax) : 0.f;
        sc[s] = e;
        lsum += e;
    }
    red[tid] = lsum;
    __syncthreads();
    for (int o = 128; o > 0; o >>= 1) {
        if (tid < o) red[tid] += red[tid + o];
        __syncthreads();
    }
    const float inv = 1.f / red[0];
    __syncthreads();
    for (int s = tid; s < Ss; s += 256) out[b * Ss + s] = sc[s] * inv;
}

// ---------------------------------------------------------------------------
extern "C" void kernel_launch(void* const* d_in, const int* in_sizes, int n_in,
                              void* d_out, int out_size) {
    const float* hidden  = (const float*)d_in[0];
    const float* enc     = (const float*)d_in[1];
    const float* W       = (const float*)d_in[2];
    const float* bias    = (const float*)d_in[3];
    const float* v       = (const float*)d_in[4];
    const int*   src_len = (const int*)d_in[5];
    float* out = (float*)d_out;

    cudaFuncSetAttribute(gemm_tanh_kernel,
                         cudaFuncAttributeMaxDynamicSharedMemorySize, SMEM_BYTES);

    wconv_kernel<<<1024, 256>>>(W);
    prep_kernel<<<dim3(32, 32), 256>>>(hidden, W, bias);
    gemm_tanh_kernel<<<dim3(NTILES, Mtot / M_TILE), 128, SMEM_BYTES>>>(enc, v);
    softmax_kernel<<<Bb, 256>>>(src_len, out);
}